// round 16
// baseline (speedup 1.0000x reference)
#include <cuda_runtime.h>
#include <cuda_fp16.h>

#define GRID_N 160
#define G2 (GRID_N*GRID_N)
#define G3 (GRID_N*GRID_N*GRID_N)
#define NS 256
#define SB 32
#define NT (NS/SB)
#define WIDTH 128
#define ACT_SHIFT (-4.59511985013459f)   /* log(1/99) */

typedef unsigned int uint;

#define MMA_F16(C, A0,A1,A2,A3, B0,B1) \
    asm volatile("mma.sync.aligned.m16n8k16.row.col.f32.f16.f16.f32 " \
        "{%0,%1,%2,%3}, {%4,%5,%6,%7}, {%8,%9}, {%0,%1,%2,%3};" \
        : "+f"((C)[0]),"+f"((C)[1]),"+f"((C)[2]),"+f"((C)[3]) \
        : "r"(A0),"r"(A1),"r"(A2),"r"(A3), "r"(B0),"r"(B1))

#define LDSM_X4(R0,R1,R2,R3, ADDR) \
    asm volatile("ldmatrix.sync.aligned.m8n8.x4.shared.b16 {%0,%1,%2,%3}, [%4];" \
        : "=r"(R0),"=r"(R1),"=r"(R2),"=r"(R3) : "r"(ADDR))

__device__ __forceinline__ float sigmoidf_(float x){ return 1.f/(1.f+__expf(-x)); }

__device__ __forceinline__ uint packh2(float a, float b){
    __half2 h = __floats2half2_rn(a, b);
    return *(uint*)&h;
}
// packed fp16 lerp+weight: ((b-a)*az + a) * wxy
__device__ __forceinline__ uint h2lerpw(uint a, uint b, uint az, uint wxy){
    __half2 A = *(__half2*)&a, B = *(__half2*)&b;
    __half2 v = __hmul2(__hfma2(*(__half2*)&az, __hsub2(B, A), A), *(__half2*)&wxy);
    return *(uint*)&v;
}
__device__ __forceinline__ uint h2add(uint a, uint b){
    __half2 v = __hadd2(*(__half2*)&a, *(__half2*)&b);
    return *(uint*)&v;
}

// fp16 voxel store: 32B/voxel = 12 half channels (24B) + fp32 sigma (4B) + pad.
__device__ uint4 g_vox[(size_t)G3 * 2];

__global__ __launch_bounds__(256)
void repack_kernel(const float* __restrict__ density, const float* __restrict__ k0)
{
    int v = blockIdx.x * 256 + threadIdx.x;
    if (v >= G3) return;
    uint4 A, B;
    A.x = packh2(k0[0*G3+v],  k0[1*G3+v]);
    A.y = packh2(k0[2*G3+v],  k0[3*G3+v]);
    A.z = packh2(k0[4*G3+v],  k0[5*G3+v]);
    A.w = packh2(k0[6*G3+v],  k0[7*G3+v]);
    B.x = packh2(k0[8*G3+v],  k0[9*G3+v]);
    B.y = packh2(k0[10*G3+v], k0[11*G3+v]);
    B.z = __float_as_uint(density[v]);
    B.w = 0u;
    g_vox[2*(size_t)v]   = A;
    g_vox[2*(size_t)v+1] = B;
}

__global__ __launch_bounds__(256, 3)
void dvgo_fused(const float* __restrict__ rays_o, const float* __restrict__ rays_d,
                const float* __restrict__ W0, const float* __restrict__ b0,
                const float* __restrict__ W1, const float* __restrict__ b1,
                const float* __restrict__ W2, const float* __restrict__ b2,
                float* __restrict__ out)
{
    __shared__ __align__(16) __half fth[SB][16];     // feats fp16 (2 A row-tiles)
    __shared__ __align__(16) __half h0s[SB][136];    // h0 fp16 (2 row-tiles)
    __shared__ __align__(16) float part2[SB][8][4];  // [s][swizzled w][rgb+pad]
    __shared__ float sigs[SB], wsm[2][SB];
    __shared__ float rts[WIDTH];                     // rayterm per unit
    __shared__ float b2s[3];
    __shared__ float accw[8][3];
    __shared__ float alphainv_s;

    const int r    = blockIdx.x;
    const int tid  = threadIdx.x;
    const int lane = tid & 31;
    const int warp = tid >> 5;       // 0..7 : N-slice (MMA), K-slice (layer2)
    const int j    = tid & 127;
    const int half = tid >> 7;

    if (tid < 3) b2s[tid] = b2[tid];

    const float ox = rays_o[3*r+0], oy = rays_o[3*r+1], oz = rays_o[3*r+2];
    const float dx = rays_d[3*r+0], dy = rays_d[3*r+1], dz = rays_d[3*r+2];

    // ---- per-ray constant: b0 + vemb@W0[12:39]  (exact fp32) ----
    {
        float inv = rsqrtf(dx*dx + dy*dy + dz*dz);
        float vd[3] = {dx*inv, dy*inv, dz*inv};
        float vemb[27];
        vemb[0]=vd[0]; vemb[1]=vd[1]; vemb[2]=vd[2];
        #pragma unroll
        for (int d=0; d<3; d++){
            #pragma unroll
            for (int k=0; k<4; k++){
                float a = vd[d] * (float)(1<<k);
                vemb[3  + d*4 + k] = sinf(a);
                vemb[15 + d*4 + k] = cosf(a);
            }
        }
        float rt = b0[j];
        #pragma unroll
        for (int i=0; i<27; i++)
            rt = fmaf(vemb[i], W0[(12+i)*WIDTH + j], rt);
        if (half == 0) rts[j] = rt;
    }

    const int m4 = lane & 3, ncol = lane >> 2;

    // ---- W1 B-fragments (fp16), warp owns N cols [16w,16w+16) ----
    uint Bq[8][2][2];
    float b1v[2][2];
    #pragma unroll
    for (int nt=0; nt<2; nt++){
        const int n = 16*warp + 8*nt + ncol;
        #pragma unroll
        for (int kt=0; kt<8; kt++){
            #pragma unroll
            for (int p=0; p<2; p++){
                int k = 16*kt + 2*m4 + 8*p;
                Bq[kt][nt][p] = packh2(W1[k*WIDTH + n], W1[(k+1)*WIDTH + n]);
            }
        }
        b1v[nt][0] = b1[16*warp + 8*nt + 2*m4];
        b1v[nt][1] = b1[16*warp + 8*nt + 2*m4 + 1];
    }

    // ---- W0 B-fragments (12 real rows, rows 12..15 zeroed) ----
    uint B0q[2][2];
    #pragma unroll
    for (int nt=0; nt<2; nt++){
        const int n = 16*warp + 8*nt + ncol;
        #pragma unroll
        for (int p=0; p<2; p++){
            int k = 2*m4 + 8*p;
            float wa = (k   < 12) ? W0[k*WIDTH + n]     : 0.f;
            float wb = (k+1 < 12) ? W0[(k+1)*WIDTH + n] : 0.f;
            B0q[nt][p] = packh2(wa, wb);
        }
    }

    // ---- W2 B-fragment: K-slice rows [16w,16w+16), N=8 (cols 0..2 real) ----
    uint B2q[2];
    #pragma unroll
    for (int p=0; p<2; p++){
        int k = 16*warp + 2*m4 + 8*p;
        float wa = (ncol < 3) ? W2[k*3 + ncol]     : 0.f;
        float wb = (ncol < 3) ? W2[(k+1)*3 + ncol] : 0.f;
        B2q[p] = packh2(wa, wb);
    }

    __syncthreads();
    float rt0[2], rt1[2];
    #pragma unroll
    for (int nt=0; nt<2; nt++){
        rt0[nt] = rts[16*warp + 8*nt + 2*m4];
        rt1[nt] = rts[16*warp + 8*nt + 2*m4 + 1];
    }

    // ldmatrix base addresses (row-tile g adds g*512 for fth, g*4352 for h0s)
    const uint faddr = (uint)__cvta_generic_to_shared(&fth[lane & 15][0]) + (uint)(lane >> 4)*16u;
    const uint haddr = (uint)__cvta_generic_to_shared(&h0s[lane & 15][0]) + (uint)(lane >> 4)*16u;

    // sampling lane decomposition: lane = ss(2)|xy(2)|qh(1); 1 sample per thread.
    // CONSECUTIVE mapping: warp w owns samples 4w..4w+3 (~0.8 voxel apart ->
    // the warp's 16 corner-regions collapse onto a few cache lines).
    const int ss  = lane >> 3;
    const int xy  = (lane >> 1) & 3;
    const int qh  = lane & 1;
    const int cxk = xy & 1, cyk = xy >> 1;
    const int smp = 4*warp + ss;        // this thread's sample (tile row)
    const char* gvb = (const char*)g_vox;

    float T = 1.f;
    float racc0=0.f, racc1=0.f, racc2=0.f;

    // incremental ray position (per tile step = SB * dt)
    const float dt  = 1.6f/255.0f;
    float px = fmaf(dx, 0.2f + (float)smp*dt, ox);
    float py = fmaf(dy, 0.2f + (float)smp*dt, oy);
    float pz = fmaf(dz, 0.2f + (float)smp*dt, oz);
    const float sx = dx * (float)SB * dt;
    const float sy = dy * (float)SB * dt;
    const float sz = dz * (float)SB * dt;

    // ---- prefetch tile 0 gathers (both z corners, 16B chunk-half) ----
    uint4 pu0, pu1; float pwxy, paz;
    {
        float gx = fminf(fmaxf((px+1.f)*79.5f, 0.f), 159.f);
        float gy = fminf(fmaxf((py+1.f)*79.5f, 0.f), 159.f);
        float gz = fminf(fmaxf((pz+1.f)*79.5f, 0.f), 159.f);
        int x0 = min((int)gx, 158), y0 = min((int)gy, 158), z0 = min((int)gz, 158);
        float ax = gx-(float)x0, ay = gy-(float)y0;
        paz = gz-(float)z0;
        uint off = (uint)(((x0+cxk)*GRID_N + (y0+cyk))*GRID_N + z0) * 32u + (uint)qh*16u;
        pu0 = __ldg((const uint4*)(gvb + off));
        pu1 = __ldg((const uint4*)(gvb + off + 32u));
        pwxy = (cxk ? ax : 1.f-ax) * (cyk ? ay : 1.f-ay);
    }

    for (int tt=0; tt<NT; tt++){
        // ====== consume prefetched gathers: fp16x2 lerp + xy-reduce ===========
        {
            uint haz  = packh2(paz,  paz);
            uint hwxy = packh2(pwxy, pwxy);
            uint4 u0 = pu0, u1 = pu1;
            float s0v = 0.f, s1v = 0.f;
            if (qh){  // extract fp32 sigma, zero non-half payload
                s0v = __uint_as_float(u0.z);  s1v = __uint_as_float(u1.z);
                u0.z = 0u; u0.w = 0u; u1.z = 0u; u1.w = 0u;
            }
            uint v0 = h2lerpw(u0.x, u1.x, haz, hwxy);
            uint v1 = h2lerpw(u0.y, u1.y, haz, hwxy);
            uint v2 = h2lerpw(u0.z, u1.z, haz, hwxy);
            uint v3 = h2lerpw(u0.w, u1.w, haz, hwxy);
            float sg = fmaf(paz, s1v - s0v, s0v) * pwxy;
            #pragma unroll
            for (int d=2; d<=4; d<<=1){
                v0 = h2add(v0, __shfl_xor_sync(0xffffffffu, v0, d));
                v1 = h2add(v1, __shfl_xor_sync(0xffffffffu, v1, d));
                v2 = h2add(v2, __shfl_xor_sync(0xffffffffu, v2, d));
                v3 = h2add(v3, __shfl_xor_sync(0xffffffffu, v3, d));
                sg += __shfl_xor_sync(0xffffffffu, sg, d);
            }
            if (xy == 0){
                *(uint4*)&fth[smp][8*qh] = make_uint4(v0, v1, v2, v3);
                if (qh) sigs[smp] = sg;          // sigma (exact fp32)
            }
        }
        // ====== advance ray + prefetch next tile ==============================
        if (tt+1 < NT){
            px += sx; py += sy; pz += sz;
            float gx = fminf(fmaxf((px+1.f)*79.5f, 0.f), 159.f);
            float gy = fminf(fmaxf((py+1.f)*79.5f, 0.f), 159.f);
            float gz = fminf(fmaxf((pz+1.f)*79.5f, 0.f), 159.f);
            int x0 = min((int)gx, 158), y0 = min((int)gy, 158), z0 = min((int)gz, 158);
            float ax = gx-(float)x0, ay = gy-(float)y0;
            paz = gz-(float)z0;
            uint off = (uint)(((x0+cxk)*GRID_N + (y0+cyk))*GRID_N + z0) * 32u + (uint)qh*16u;
            pu0 = __ldg((const uint4*)(gvb + off));
            pu1 = __ldg((const uint4*)(gvb + off + 32u));
            pwxy = (cxk ? ax : 1.f-ax) * (cyk ? ay : 1.f-ay);
        }
        __syncthreads();   // B1: fth/sigs of tile tt AND part2 of tile tt-1 visible

        // ============ deferred compositing of tile tt-1 ======================
        if (tt > 0){
            const int w2 = lane & 7;
            const int s  = 4*warp + (lane >> 3);
            float4 p = *(const float4*)&part2[s][w2 ^ (s & 7)][0];
            #pragma unroll
            for (int d=1; d<8; d<<=1){
                p.x += __shfl_xor_sync(0xffffffffu, p.x, d);
                p.y += __shfl_xor_sync(0xffffffffu, p.y, d);
                p.z += __shfl_xor_sync(0xffffffffu, p.z, d);
            }
            if (w2 == 0){
                float w = wsm[(tt-1)&1][s];
                racc0 = fmaf(w, sigmoidf_(p.x + b2s[0]), racc0);
                racc1 = fmaf(w, sigmoidf_(p.y + b2s[1]), racc1);
                racc2 = fmaf(w, sigmoidf_(p.z + b2s[2]), racc2);
            }
        }

        // ============ transmittance (warp 0): full-warp log/exp scan ==========
        if (warp == 0){
            float e  = __expf(sigs[lane] + ACT_SHIFT);
            float a  = 1.f - rsqrtf(1.f + e);
            float lg = __logf(1.f - a + 1e-10f);
            float sc = lg;
            #pragma unroll
            for (int d=1; d<32; d<<=1){
                float n = __shfl_up_sync(0xffffffffu, sc, d);
                if (lane >= d) sc += n;
            }
            wsm[tt&1][lane] = a * T * __expf(sc - lg);   // exclusive prefix
            T *= __expf(__shfl_sync(0xffffffffu, sc, 31));
            if (tt == NT-1 && lane == 0) alphainv_s = T;
        }

        // ============ layer0: fp16 MMA per row-tile, rayterm as C init ========
        #pragma unroll
        for (int g=0; g<2; g++){
            float c[2][4];
            #pragma unroll
            for (int nt=0; nt<2; nt++){
                c[nt][0]=rt0[nt]; c[nt][1]=rt1[nt];
                c[nt][2]=rt0[nt]; c[nt][3]=rt1[nt];
            }
            uint a0,a1,a2,a3;
            LDSM_X4(a0,a1,a2,a3, faddr + (uint)g*512u);
            #pragma unroll
            for (int nt=0; nt<2; nt++)
                MMA_F16(c[nt], a0,a1,a2,a3, B0q[nt][0], B0q[nt][1]);
            const int row = lane >> 2;
            #pragma unroll
            for (int nt=0; nt<2; nt++){
                const int n0 = 16*warp + 8*nt + 2*m4;
                *(uint*)&h0s[16*g + row][n0]     = packh2(fmaxf(c[nt][0],0.f), fmaxf(c[nt][1],0.f));
                *(uint*)&h0s[16*g + row + 8][n0] = packh2(fmaxf(c[nt][2],0.f), fmaxf(c[nt][3],0.f));
            }
        }
        __syncthreads();   // B2: h0s visible

        // ============ layer1 MMA + layer2 MMA fused, per row-tile =============
        #pragma unroll
        for (int g=0; g<2; g++){
            float c0[2][4];
            #pragma unroll
            for (int nt=0; nt<2; nt++){
                c0[nt][0]=b1v[nt][0]; c0[nt][1]=b1v[nt][1];
                c0[nt][2]=b1v[nt][0]; c0[nt][3]=b1v[nt][1];
            }
            #pragma unroll
            for (int kt=0; kt<8; kt++){
                uint a0,a1,a2,a3;
                LDSM_X4(a0,a1,a2,a3, haddr + (uint)g*4352u + (uint)kt*32u);
                #pragma unroll
                for (int nt=0; nt<2; nt++)
                    MMA_F16(c0[nt], a0,a1,a2,a3, Bq[kt][nt][0], Bq[kt][nt][1]);
            }
            // relu + pack layer1 C directly into layer2 A-fragment
            uint a0 = packh2(fmaxf(c0[0][0],0.f), fmaxf(c0[0][1],0.f));
            uint a1 = packh2(fmaxf(c0[0][2],0.f), fmaxf(c0[0][3],0.f));
            uint a2 = packh2(fmaxf(c0[1][0],0.f), fmaxf(c0[1][1],0.f));
            uint a3 = packh2(fmaxf(c0[1][2],0.f), fmaxf(c0[1][3],0.f));
            float cc[4] = {0.f, 0.f, 0.f, 0.f};
            MMA_F16(cc, a0,a1,a2,a3, B2q[0], B2q[1]);
            const int row = lane >> 2;
            if (m4 < 2){
                *(float2*)&part2[16*g + row][warp ^ row][2*m4]     = make_float2(cc[0], cc[1]);
                *(float2*)&part2[16*g + row + 8][warp ^ row][2*m4] = make_float2(cc[2], cc[3]);
            }
        }
        // no B3: next tile's B1 orders part2 writes before the deferred composite
    }

    __syncthreads();   // final: part2 of tile NT-1 visible
    {
        const int w2 = lane & 7;
        const int s  = 4*warp + (lane >> 3);
        float4 p = *(const float4*)&part2[s][w2 ^ (s & 7)][0];
        #pragma unroll
        for (int d=1; d<8; d<<=1){
            p.x += __shfl_xor_sync(0xffffffffu, p.x, d);
            p.y += __shfl_xor_sync(0xffffffffu, p.y, d);
            p.z += __shfl_xor_sync(0xffffffffu, p.z, d);
        }
        if (w2 == 0){
            float w = wsm[(NT-1)&1][s];
            racc0 = fmaf(w, sigmoidf_(p.x + b2s[0]), racc0);
            racc1 = fmaf(w, sigmoidf_(p.y + b2s[1]), racc1);
            racc2 = fmaf(w, sigmoidf_(p.z + b2s[2]), racc2);
        }
    }

    // merge accumulator lanes 8,16,24 into lane 0, then block reduction
    racc0 += __shfl_down_sync(0xffffffffu, racc0, 16);
    racc1 += __shfl_down_sync(0xffffffffu, racc1, 16);
    racc2 += __shfl_down_sync(0xffffffffu, racc2, 16);
    racc0 += __shfl_down_sync(0xffffffffu, racc0, 8);
    racc1 += __shfl_down_sync(0xffffffffu, racc1, 8);
    racc2 += __shfl_down_sync(0xffffffffu, racc2, 8);
    if (lane == 0){
        accw[warp][0] = racc0; accw[warp][1] = racc1; accw[warp][2] = racc2;
    }
    __syncthreads();
    if (tid < 3){
        float s = alphainv_s;
        #pragma unroll
        for (int w=0; w<8; w++) s += accw[w][tid];
        out[3*r + tid] = s;
    }
}

extern "C" void kernel_launch(void* const* d_in, const int* in_sizes, int n_in,
                              void* d_out, int out_size)
{
    const float* rays_o  = (const float*)d_in[0];
    const float* rays_d  = (const float*)d_in[1];
    const float* density = (const float*)d_in[2];
    const float* k0      = (const float*)d_in[3];
    const float* W0      = (const float*)d_in[4];
    const float* b0      = (const float*)d_in[5];
    const float* W1      = (const float*)d_in[6];
    const float* b1      = (const float*)d_in[7];
    const float* W2      = (const float*)d_in[8];
    const float* b2      = (const float*)d_in[9];
    float* out = (float*)d_out;

    repack_kernel<<<(G3 + 255)/256, 256>>>(density, k0);

    int n_rays = in_sizes[0] / 3;
    dvgo_fused<<<n_rays, 256>>>(rays_o, rays_d,
                                W0, b0, W1, b1, W2, b2, out);
}